// round 11
// baseline (speedup 1.0000x reference)
#include <cuda_runtime.h>
#include <cuda_bf16.h>
#include <cstdint>

// Problem constants (fixed by the reference)
#define BATCH    8192
#define ITEMS    10000
#define ITEMS4   (ITEMS / 4)   // 2500 float4 per row
#define TPB      256

// Scratch (allocation-free rule: __device__ globals). g_done_ctr starts 0
// (zero-init) and is reset to 0 by the last CTA each call -> deterministic
// across graph replays.
__device__ float        g_row_loss[BATCH];
__device__ unsigned int g_done_ctr;

// Streaming load: read-only + L1 no-allocate (keeps W resident in L1,
// saves L1tex fill bandwidth for the one-touch h/t streams).
__device__ __forceinline__ float4 ldg_stream(const float4* p) {
    float4 v;
    asm("ld.global.nc.L1::no_allocate.v4.f32 {%0,%1,%2,%3}, [%4];"
        : "=f"(v.x), "=f"(v.y), "=f"(v.z), "=f"(v.w)
        : "l"(p));
    return v;
}

// ---------------------------------------------------------------------------
// One CTA per row (grid = BATCH): q = relu(dot(h,W)+b), nq = relu(dot(t,W)+b),
// loss = is_done ? 0 : |r + disc*nq - q|. The last CTA to finish performs the
// fixed-order final sum and writes out[0] = sum / B (no second launch).
// ---------------------------------------------------------------------------
__global__ __launch_bounds__(TPB, 8)
void dq_row_kernel(const float* __restrict__ hidden,   // [B, ITEMS]
                   const float* __restrict__ target,   // [B, ITEMS]
                   const float* __restrict__ W,        // [ITEMS]
                   const float* __restrict__ bptr,     // [1]
                   const float* __restrict__ rewards,  // [B]
                   const float* __restrict__ discount, // scalar
                   const unsigned char* __restrict__ is_done, // [B] bool
                   float* __restrict__ out)
{
    const int row  = blockIdx.x;
    const int tid  = threadIdx.x;
    const int warp = tid >> 5;
    const int lane = tid & 31;

    const float4* __restrict__ h4 =
        reinterpret_cast<const float4*>(hidden + (size_t)row * ITEMS);
    const float4* __restrict__ t4 =
        reinterpret_cast<const float4*>(target + (size_t)row * ITEMS);
    const float4* __restrict__ w4 = reinterpret_cast<const float4*>(W);

    float qa = 0.0f;   // dot(hidden_row, W)
    float na = 0.0f;   // dot(target_row, W)

    // 2500 float4 per row / 256 threads -> ~10 trips/thread.
    #pragma unroll 2
    for (int i = tid; i < ITEMS4; i += TPB) {
        float4 h = ldg_stream(&h4[i]);   // L1 no-allocate stream
        float4 t = ldg_stream(&t4[i]);   // L1 no-allocate stream
        float4 w = __ldg(&w4[i]);        // L1-resident hot vector
        qa = fmaf(h.x, w.x, qa); qa = fmaf(h.y, w.y, qa);
        qa = fmaf(h.z, w.z, qa); qa = fmaf(h.w, w.w, qa);
        na = fmaf(t.x, w.x, na); na = fmaf(t.y, w.y, na);
        na = fmaf(t.z, w.z, na); na = fmaf(t.w, w.w, na);
    }

    // Warp reduction (two values at once)
    #pragma unroll
    for (int off = 16; off > 0; off >>= 1) {
        qa += __shfl_down_sync(0xFFFFFFFFu, qa, off);
        na += __shfl_down_sync(0xFFFFFFFFu, na, off);
    }

    __shared__ float s_q[8];
    __shared__ float s_n[8];
    if (lane == 0) { s_q[warp] = qa; s_n[warp] = na; }
    __syncthreads();

    if (warp == 0) {
        qa = (lane < 8) ? s_q[lane] : 0.0f;
        na = (lane < 8) ? s_n[lane] : 0.0f;
        #pragma unroll
        for (int off = 4; off > 0; off >>= 1) {
            qa += __shfl_down_sync(0xFFFFFFFFu, qa, off);
            na += __shfl_down_sync(0xFFFFFFFFu, na, off);
        }
        if (lane == 0) {
            const float b = bptr[0];
            const float q  = fmaxf(qa + b, 0.0f);
            const float nq = fmaxf(na + b, 0.0f);
            float loss = fabsf(rewards[row] + discount[0] * nq - q);
            if (is_done[row]) loss = 0.0f;
            g_row_loss[row] = loss;
        }
    }

    // ---- last-CTA-done final reduction (fixed-order, deterministic) ----
    __shared__ bool s_last;
    __threadfence();                       // publish g_row_loss[row]
    if (tid == 0) {
        unsigned int prev = atomicAdd(&g_done_ctr, 1u);
        s_last = (prev == (unsigned int)(BATCH - 1));
    }
    __syncthreads();
    if (!s_last) return;

    // Last CTA: fixed-order sum of all BATCH losses (float4 loads, L2-hot).
    const float4* __restrict__ l4 = reinterpret_cast<const float4*>(g_row_loss);
    float acc = 0.0f;
    #pragma unroll
    for (int i = tid; i < BATCH / 4; i += TPB) {
        float4 v = l4[i];
        acc += (v.x + v.y) + (v.z + v.w);
    }

    #pragma unroll
    for (int off = 16; off > 0; off >>= 1)
        acc += __shfl_down_sync(0xFFFFFFFFu, acc, off);

    __shared__ float s_f[8];
    if (lane == 0) s_f[warp] = acc;
    __syncthreads();

    if (warp == 0) {
        acc = (lane < 8) ? s_f[lane] : 0.0f;
        #pragma unroll
        for (int off = 4; off > 0; off >>= 1)
            acc += __shfl_down_sync(0xFFFFFFFFu, acc, off);
        if (lane == 0) {
            out[0] = acc / (float)BATCH;
            g_done_ctr = 0;                // reset for next graph replay
        }
    }
}

// ---------------------------------------------------------------------------
// Launch. Input order per metadata:
//   0 hidden_states [B*ITEMS] f32
//   1 actions       [B]       i32   (unused by the math)
//   2 rewards       [B]       f32
//   3 discount      [1]       f32
//   4 targetQs_s    [B*ITEMS] f32
//   5 is_done       [B]       bool
//   6 W             [ITEMS]   f32
//   7 b             [1]       f32
// ---------------------------------------------------------------------------
extern "C" void kernel_launch(void* const* d_in, const int* in_sizes, int n_in,
                              void* d_out, int out_size)
{
    const float* hidden   = (const float*)d_in[0];
    const float* rewards  = (const float*)d_in[2];
    const float* discount = (const float*)d_in[3];
    const float* target   = (const float*)d_in[4];
    const unsigned char* is_done = (const unsigned char*)d_in[5];
    const float* W        = (const float*)d_in[6];
    const float* b        = (const float*)d_in[7];
    float* out = (float*)d_out;

    dq_row_kernel<<<BATCH, TPB>>>(hidden, target, W, b,
                                  rewards, discount, is_done, out);
}